// round 12
// baseline (speedup 1.0000x reference)
#include <cuda_runtime.h>
#include <cuda_fp16.h>
#include <cstdint>

// Problem constants
#define BATCH 32
#define TT    4096
#define HH    256
#define TB    (TT * BATCH)     // 131072 rows of enc

// -------------------- scratch (static device arrays) -----------------------
__device__ float g_pre1[BATCH * HH];            // W1*hidden + bias
__device__ float g_scores[BATCH * TT];          // transposed scores [b][t]
// Pre-swizzled B tiles (fp16): [chunk 0..3][256 n][64 k]
__device__ unsigned char g_bpk[4 * 32768];      // 128KB

// -------------------- helpers ----------------------------------------------
__device__ __forceinline__ uint32_t smem_u32(const void* p) {
    uint32_t a;
    asm("{ .reg .u64 t; cvta.to.shared.u64 t, %1; cvt.u32.u64 %0, t; }" : "=r"(a) : "l"(p));
    return a;
}
__device__ __forceinline__ void cp16(void* smem_dst, const void* gsrc) {
    unsigned s = (unsigned)__cvta_generic_to_shared(smem_dst);
    asm volatile("cp.async.cg.shared.global [%0], [%1], 16;\n" :: "r"(s), "l"(gsrc));
}
#define CP_COMMIT() asm volatile("cp.async.commit_group;\n" ::: "memory")
#define CP_WAIT0()  asm volatile("cp.async.wait_group 0;\n" ::: "memory")

__device__ __forceinline__ uint32_t pack_f16x2(float x, float y) {
    uint32_t r;
    asm("cvt.rn.f16x2.f32 %0, %1, %2;" : "=r"(r) : "f"(y), "f"(x));
    return r;
}
__device__ __forceinline__ void ldsm4(uint32_t* r, uint32_t addr) {
    asm volatile("ldmatrix.sync.aligned.m8n8.x4.shared.b16 {%0,%1,%2,%3}, [%4];"
                 : "=r"(r[0]), "=r"(r[1]), "=r"(r[2]), "=r"(r[3]) : "r"(addr));
}
__device__ __forceinline__ void mma16816(float* c, const uint32_t* a, uint32_t b0, uint32_t b1) {
    asm volatile("mma.sync.aligned.m16n8k16.row.col.f32.f16.f16.f32 "
                 "{%0,%1,%2,%3}, {%4,%5,%6,%7}, {%8,%9}, {%0,%1,%2,%3};"
                 : "+f"(c[0]), "+f"(c[1]), "+f"(c[2]), "+f"(c[3])
                 : "r"(a[0]), "r"(a[1]), "r"(a[2]), "r"(a[3]), "r"(b0), "r"(b1));
}

// ---------------------------------------------------------------------------
// Kernel 1 (fused init, PROVEN 1280x256 layout):
//   blocks [0,1024) pre1 (warp per output), [1024,1280) bpack.
// ---------------------------------------------------------------------------
__global__ void init_kernel(const float* __restrict__ hidden,
                            const float* __restrict__ attn_w,
                            const float* __restrict__ attn_b) {
    if (blockIdx.x < 1024) {
        int gw   = (blockIdx.x * 256 + threadIdx.x) >> 5;   // 0..8191
        int lane = threadIdx.x & 31;
        int b = gw >> 8, h = gw & 255;
        const float4* hp = (const float4*)(hidden + (size_t)b * HH);
        const float4* wp = (const float4*)(attn_w + (size_t)h * (2 * HH));
        float4 x0 = hp[lane],      w0 = wp[lane];
        float4 x1 = hp[lane + 32], w1 = wp[lane + 32];
        float s = x0.x*w0.x + x0.y*w0.y + x0.z*w0.z + x0.w*w0.w
                + x1.x*w1.x + x1.y*w1.y + x1.z*w1.z + x1.w*w1.w;
        #pragma unroll
        for (int o = 16; o; o >>= 1) s += __shfl_xor_sync(0xffffffffu, s, o);
        if (lane == 0) g_pre1[gw] = s + attn_b[h];
    } else {
        int idx = (blockIdx.x - 1024) * 256 + threadIdx.x;  // 0..65535
        int c = idx >> 14;
        int r = idx & 16383;
        int n = r >> 6;
        int k = r & 63;
        float val = attn_w[(size_t)n * 512 + 256 + c * 64 + k];
        __half hv = __float2half_rn(val);
        uint32_t o  = (uint32_t)(k * 2) ^ ((uint32_t)(n & 7) * 16);
        uint32_t so = (uint32_t)n * 128 + o;
        *(uint16_t*)(g_bpk + c * 32768 + so) = __half_as_ushort(hv);
    }
}

// ---------------------------------------------------------------------------
// Kernel 2: single-term fp16 HMMA GEMM + fused epilogue.
// CTA: 64 rows x 256 cols, 128 thr (4 warps, wn = wid), warp tile 64x64.
// B read ONCE per CTA (no wm duplication); A-frag reuse x4 (mi).
// Occupancy 2 (8 warps/SM).
// SMEM: As [2 buf][64][64] fp16  = 16KB @ 0       (epilogue: ps aliases @0)
//       Bs [2 buf][256][64] fp16 = 64KB @ 16384
//       pre1s [32][260] fp32     = 33280 @ 81920  (filled in prologue)
// ---------------------------------------------------------------------------
#define SMEM_PRE1 81920
#define SMEM_DYN  115200     // x2 CTAs = 230400 <= 233472

__global__ __launch_bounds__(128, 2)
void energy_kernel(const float* __restrict__ enc, const float* __restrict__ v) {
    extern __shared__ __align__(1024) unsigned char smem[];
    const uint32_t sb = smem_u32(smem);
    const int tid = threadIdx.x, wn = tid >> 5, L = tid & 31;
    const int r0 = blockIdx.x * 64;

    float acc[4][8][4];
    #pragma unroll
    for (int i = 0; i < 4; i++)
        #pragma unroll
        for (int j = 0; j < 8; j++)
            #pragma unroll
            for (int q = 0; q < 4; q++) acc[i][j][q] = 0.f;

    float4 a_st[4];

    auto ldg_A = [&](int c) {
        #pragma unroll
        for (int it = 0; it < 4; it++) {
            int idx = tid + it * 128;          // 0..511 (8-float units)
            int row = idx >> 3, c8 = idx & 7;
            const float4* p = (const float4*)(enc + (size_t)(r0 + row) * HH + c * 64 + c8 * 8);
            // one float4 now, second later in sts (keep reg use low): load both
            a_st[it] = p[0];
            // second half loaded in sts_A via direct ldg would break pipeline;
            // instead store both halves: use two stage arrays
        }
    };
    // second half staged separately to keep the same LDG->STS pipeline
    float4 a_st2[4];
    auto ldg_A2 = [&](int c) {
        #pragma unroll
        for (int it = 0; it < 4; it++) {
            int idx = tid + it * 128;
            int row = idx >> 3, c8 = idx & 7;
            const float4* p = (const float4*)(enc + (size_t)(r0 + row) * HH + c * 64 + c8 * 8);
            a_st2[it] = p[1];
        }
    };
    auto sts_A = [&](int buf) {
        #pragma unroll
        for (int it = 0; it < 4; it++) {
            int idx = tid + it * 128;
            int row = idx >> 3, c8 = idx & 7;
            uint4 hv = make_uint4(pack_f16x2(a_st[it].x,  a_st[it].y),
                                  pack_f16x2(a_st[it].z,  a_st[it].w),
                                  pack_f16x2(a_st2[it].x, a_st2[it].y),
                                  pack_f16x2(a_st2[it].z, a_st2[it].w));
            uint32_t off = (uint32_t)row * 128 + (((uint32_t)c8 * 16) ^ ((uint32_t)(row & 7) * 16));
            *(uint4*)(smem + buf * 8192 + off) = hv;
        }
    };
    auto cpy_B = [&](int buf, int c) {
        #pragma unroll
        for (int st = 0; st < 16; st++) {
            int off = (tid + st * 128) * 16;
            cp16(smem + 16384 + buf * 32768 + off, g_bpk + c * 32768 + off);
        }
        CP_COMMIT();
    };

    const int lrow16 = L & 15;
    const uint32_t lcol = (uint32_t)(L >> 4) * 16;

    auto mma_chunk = [&](int buf) {
        const uint32_t aB = sb + (uint32_t)buf * 8192;
        const uint32_t bB = sb + 16384u + (uint32_t)buf * 32768;
        #pragma unroll
        for (int ks = 0; ks < 4; ks++) {
            const uint32_t kb = (uint32_t)ks * 32;
            uint32_t ah[4][4], bf[4][4];
            #pragma unroll
            for (int mi = 0; mi < 4; mi++) {
                int arow = mi * 16 + lrow16;
                uint32_t aoff = (uint32_t)arow * 128 + ((kb + lcol) ^ ((uint32_t)(arow & 7) * 16));
                ldsm4(ah[mi], aB + aoff);
            }
            #pragma unroll
            for (int nj = 0; nj < 4; nj++) {
                int brow = wn * 64 + nj * 16 + lrow16;
                uint32_t boff = (uint32_t)brow * 128 + ((kb + lcol) ^ ((uint32_t)(brow & 7) * 16));
                ldsm4(bf[nj], bB + boff);
            }
            #pragma unroll
            for (int nj = 0; nj < 4; nj++)
                #pragma unroll
                for (int mi = 0; mi < 4; mi++) {
                    mma16816(acc[mi][nj * 2 + 0], ah[mi], bf[nj][0], bf[nj][2]);
                    mma16816(acc[mi][nj * 2 + 1], ah[mi], bf[nj][1], bf[nj][3]);
                }
        }
    };

    // ---- prologue: B chunk0 cp.async, pre1 staging, A chunk0 ----
    cpy_B(0, 0);
    {
        float* pre1s = (float*)(smem + SMEM_PRE1);      // pitch 260
        #pragma unroll
        for (int i = 0; i < 16; i++) {
            int idx4 = tid + i * 128;                   // 0..2047 float4 units
            int bb = idx4 >> 6, cc4 = (idx4 & 63) * 4;
            *(float4*)(pre1s + bb * 260 + cc4) = *(const float4*)(g_pre1 + bb * 256 + cc4);
        }
    }
    ldg_A(0); ldg_A2(0);
    sts_A(0);
    CP_WAIT0();
    __syncthreads();

    // ---- pipelined mainloop over 4 chunks ----
    #pragma unroll
    for (int c = 0; c < 4; c++) {
        const int buf = c & 1;
        if (c < 3) { ldg_A(c + 1); ldg_A2(c + 1); cpy_B(buf ^ 1, c + 1); }
        mma_chunk(buf);
        if (c < 3) {
            sts_A(buf ^ 1);
            CP_WAIT0();
        }
        __syncthreads();
    }

    // ---- epilogue: +pre1 (float2 smem), relu, dot v (ldg float2), reduce ----
    float* pre1s = (float*)(smem + SMEM_PRE1);
    float* ps    = (float*)smem;                        // [64][4] aliases dead As
    #pragma unroll
    for (int mi = 0; mi < 4; mi++) {
        #pragma unroll
        for (int p = 0; p < 2; p++) {
            int row = mi * 16 + (L >> 2) + p * 8;       // 0..63
            int bb  = row & 31;
            const float* pr = pre1s + bb * 260;
            float s = 0.f;
            #pragma unroll
            for (int nj = 0; nj < 8; nj++) {
                int n0 = wn * 64 + nj * 8 + (L & 3) * 2;
                float2 pf = *(const float2*)(pr + n0);
                float2 vv = __ldg((const float2*)(v + n0));
                float e0 = acc[mi][nj][p * 2 + 0] + pf.x;
                float e1 = acc[mi][nj][p * 2 + 1] + pf.y;
                s += fmaxf(e0, 0.f) * vv.x + fmaxf(e1, 0.f) * vv.y;
            }
            s += __shfl_xor_sync(0xffffffffu, s, 1);
            s += __shfl_xor_sync(0xffffffffu, s, 2);
            if ((L & 3) == 0) ps[row * 4 + wn] = s;
        }
    }
    __syncthreads();
    if (tid < 64) {
        float tot = ps[tid * 4] + ps[tid * 4 + 1] + ps[tid * 4 + 2] + ps[tid * 4 + 3];
        g_scores[(size_t)(tid & 31) * TT + blockIdx.x * 2 + (tid >> 5)] = tot;
    }
}

// ---------------------------------------------------------------------------
// Kernel 3: softmax over T per batch row (float4 vectorized).
// ---------------------------------------------------------------------------
__global__ void softmax_kernel(float* __restrict__ out) {
    int b = blockIdx.x, tid = threadIdx.x;
    __shared__ float red[32];
    __shared__ float bc;
    const float4* sc4 = (const float4*)(g_scores + (size_t)b * TT);

    float4 x = sc4[tid];
    float m = fmaxf(fmaxf(x.x, x.y), fmaxf(x.z, x.w));
    #pragma unroll
    for (int o = 16; o; o >>= 1) m = fmaxf(m, __shfl_xor_sync(0xffffffffu, m, o));
    if ((tid & 31) == 0) red[tid >> 5] = m;
    __syncthreads();
    if (tid < 32) {
        float t = red[tid];
        #pragma unroll
        for (int o = 16; o; o >>= 1) t = fmaxf(t, __shfl_xor_sync(0xffffffffu, t, o));
        if (tid == 0) bc = t;
    }
    __syncthreads();
    m = bc;
    float e0 = expf(x.x - m), e1 = expf(x.y - m), e2 = expf(x.z - m), e3 = expf(x.w - m);
    float ssum = (e0 + e1) + (e2 + e3);
    #pragma unroll
    for (int o = 16; o; o >>= 1) ssum += __shfl_xor_sync(0xffffffffu, ssum, o);
    if ((tid & 31) == 0) red[tid >> 5] = ssum;
    __syncthreads();
    if (tid < 32) {
        float t = red[tid];
        #pragma unroll
        for (int o = 16; o; o >>= 1) t += __shfl_xor_sync(0xffffffffu, t, o);
        if (tid == 0) bc = 1.f / t;
    }
    __syncthreads();
    float inv = bc;
    float4* ob4 = (float4*)(out + (size_t)b * TT);
    ob4[tid] = make_float4(e0 * inv, e1 * inv, e2 * inv, e3 * inv);
}

// ---------------------------------------------------------------------------
extern "C" void kernel_launch(void* const* d_in, const int* in_sizes, int n_in,
                              void* d_out, int out_size) {
    const float* hidden = (const float*)d_in[0];   // [B, H]
    const float* enc    = (const float*)d_in[1];   // [T, B, H]
    const float* attn_w = (const float*)d_in[2];   // [H, 2H]
    const float* attn_b = (const float*)d_in[3];   // [H]
    const float* v      = (const float*)d_in[4];   // [H]
    float* out = (float*)d_out;                    // [B, 1, T]

    cudaFuncSetAttribute(energy_kernel,
                         cudaFuncAttributeMaxDynamicSharedMemorySize, SMEM_DYN);

    init_kernel<<<1280, 256>>>(hidden, attn_w, attn_b);
    energy_kernel<<<TB / 64, 128, SMEM_DYN>>>(enc, v);
    softmax_kernel<<<BATCH, 1024>>>(out);
}

// round 13
// speedup vs baseline: 1.4262x; 1.4262x over previous
#include <cuda_runtime.h>
#include <cuda_fp16.h>
#include <cstdint>

// Problem constants
#define BATCH 32
#define TT    4096
#define HH    256
#define TB    (TT * BATCH)     // 131072 rows of enc

// -------------------- scratch (static device arrays) -----------------------
__device__ float g_pre1[BATCH * HH];            // W1*hidden + bias
__device__ float g_scores[BATCH * TT];          // transposed scores [b][t]
// Pre-swizzled B tiles (fp16): [chunk 0..3][256 n][64 k]
__device__ unsigned char g_bpk[4 * 32768];      // 128KB

// -------------------- helpers ----------------------------------------------
__device__ __forceinline__ uint32_t smem_u32(const void* p) {
    uint32_t a;
    asm("{ .reg .u64 t; cvta.to.shared.u64 t, %1; cvt.u32.u64 %0, t; }" : "=r"(a) : "l"(p));
    return a;
}
__device__ __forceinline__ void cp16(void* smem_dst, const void* gsrc) {
    unsigned s = (unsigned)__cvta_generic_to_shared(smem_dst);
    asm volatile("cp.async.cg.shared.global [%0], [%1], 16;\n" :: "r"(s), "l"(gsrc));
}
#define CP_COMMIT() asm volatile("cp.async.commit_group;\n" ::: "memory")
#define CP_WAIT0()  asm volatile("cp.async.wait_group 0;\n" ::: "memory")

__device__ __forceinline__ uint32_t pack_f16x2(float x, float y) {
    uint32_t r;
    asm("cvt.rn.f16x2.f32 %0, %1, %2;" : "=r"(r) : "f"(y), "f"(x));
    return r;
}
__device__ __forceinline__ void ldsm4(uint32_t* r, uint32_t addr) {
    asm volatile("ldmatrix.sync.aligned.m8n8.x4.shared.b16 {%0,%1,%2,%3}, [%4];"
                 : "=r"(r[0]), "=r"(r[1]), "=r"(r[2]), "=r"(r[3]) : "r"(addr));
}
__device__ __forceinline__ void mma16816(float* c, const uint32_t* a, uint32_t b0, uint32_t b1) {
    asm volatile("mma.sync.aligned.m16n8k16.row.col.f32.f16.f16.f32 "
                 "{%0,%1,%2,%3}, {%4,%5,%6,%7}, {%8,%9}, {%0,%1,%2,%3};"
                 : "+f"(c[0]), "+f"(c[1]), "+f"(c[2]), "+f"(c[3])
                 : "r"(a[0]), "r"(a[1]), "r"(a[2]), "r"(a[3]), "r"(b0), "r"(b1));
}

// ---------------------------------------------------------------------------
// Kernel 1 (fused init, PROVEN 1280x256 layout):
//   blocks [0,1024) pre1 (warp per output), [1024,1280) bpack.
// ---------------------------------------------------------------------------
__global__ void init_kernel(const float* __restrict__ hidden,
                            const float* __restrict__ attn_w,
                            const float* __restrict__ attn_b) {
    if (blockIdx.x < 1024) {
        int gw   = (blockIdx.x * 256 + threadIdx.x) >> 5;   // 0..8191
        int lane = threadIdx.x & 31;
        int b = gw >> 8, h = gw & 255;
        const float4* hp = (const float4*)(hidden + (size_t)b * HH);
        const float4* wp = (const float4*)(attn_w + (size_t)h * (2 * HH));
        float4 x0 = hp[lane],      w0 = wp[lane];
        float4 x1 = hp[lane + 32], w1 = wp[lane + 32];
        float s = x0.x*w0.x + x0.y*w0.y + x0.z*w0.z + x0.w*w0.w
                + x1.x*w1.x + x1.y*w1.y + x1.z*w1.z + x1.w*w1.w;
        #pragma unroll
        for (int o = 16; o; o >>= 1) s += __shfl_xor_sync(0xffffffffu, s, o);
        if (lane == 0) g_pre1[gw] = s + attn_b[h];
    } else {
        int idx = (blockIdx.x - 1024) * 256 + threadIdx.x;  // 0..65535
        int c = idx >> 14;
        int r = idx & 16383;
        int n = r >> 6;
        int k = r & 63;
        float val = attn_w[(size_t)n * 512 + 256 + c * 64 + k];
        __half hv = __float2half_rn(val);
        uint32_t o  = (uint32_t)(k * 2) ^ ((uint32_t)(n & 7) * 16);
        uint32_t so = (uint32_t)n * 128 + o;
        *(uint16_t*)(g_bpk + c * 32768 + so) = __half_as_ushort(hv);
    }
}

// ---------------------------------------------------------------------------
// Kernel 2: single-term fp16 HMMA GEMM + fused epilogue.
// CTA: 64 rows x 256 cols, 128 thr (4 warps, wn = wid), warp tile 64x64.
// B read once per CTA per chunk (no wm duplication); A-frag reuse x4 (mi).
// Occupancy 2 (8 warps/SM). Staging registers have SHORT live ranges:
//   cp.async B prefetch issued before the MMA block (0 regs);
//   A LDG->cvt->STS for the next chunk happens AFTER the MMA block, in two
//   16-reg transient batches (latency covered by the co-resident CTA).
// SMEM: As [2 buf][64][64] fp16  = 16KB @ 0       (epilogue: ps aliases @0)
//       Bs [2 buf][256][64] fp16 = 64KB @ 16384
//       pre1s [32][260] fp32     = 33280 @ 81920  (filled in prologue)
// ---------------------------------------------------------------------------
#define SMEM_PRE1 81920
#define SMEM_DYN  115200     // x2 CTAs = 230400 <= 233472

__global__ __launch_bounds__(128, 2)
void energy_kernel(const float* __restrict__ enc, const float* __restrict__ v) {
    extern __shared__ __align__(1024) unsigned char smem[];
    const uint32_t sb = smem_u32(smem);
    const int tid = threadIdx.x, wn = tid >> 5, L = tid & 31;
    const int r0 = blockIdx.x * 64;

    float acc[4][8][4];
    #pragma unroll
    for (int i = 0; i < 4; i++)
        #pragma unroll
        for (int j = 0; j < 8; j++)
            #pragma unroll
            for (int q = 0; q < 4; q++) acc[i][j][q] = 0.f;

    // One batch: rows it = h*2, h*2+1 -> load 2x float4, convert, store uint4.
    // All registers die at the end of the call (short live range).
    auto ldgsts_A_batch = [&](int buf, int c, int h) {
        #pragma unroll
        for (int it = h * 2; it < h * 2 + 2; it++) {
            int idx = tid + it * 128;          // 0..511 (8-float units)
            int row = idx >> 3, c8 = idx & 7;
            const float4* p = (const float4*)(enc + (size_t)(r0 + row) * HH + c * 64 + c8 * 8);
            float4 a0 = p[0], a1 = p[1];
            uint4 hv = make_uint4(pack_f16x2(a0.x, a0.y), pack_f16x2(a0.z, a0.w),
                                  pack_f16x2(a1.x, a1.y), pack_f16x2(a1.z, a1.w));
            uint32_t off = (uint32_t)row * 128 + (((uint32_t)c8 * 16) ^ ((uint32_t)(row & 7) * 16));
            *(uint4*)(smem + buf * 8192 + off) = hv;
        }
    };
    auto cpy_B = [&](int buf, int c) {
        #pragma unroll
        for (int st = 0; st < 16; st++) {
            int off = (tid + st * 128) * 16;
            cp16(smem + 16384 + buf * 32768 + off, g_bpk + c * 32768 + off);
        }
        CP_COMMIT();
    };

    const int lrow16 = L & 15;
    const uint32_t lcol = (uint32_t)(L >> 4) * 16;

    auto mma_chunk = [&](int buf) {
        const uint32_t aB = sb + (uint32_t)buf * 8192;
        const uint32_t bB = sb + 16384u + (uint32_t)buf * 32768;
        #pragma unroll
        for (int ks = 0; ks < 4; ks++) {
            const uint32_t kb = (uint32_t)ks * 32;
            uint32_t ah[4][4], bf[4][4];
            #pragma unroll
            for (int mi = 0; mi < 4; mi++) {
                int arow = mi * 16 + lrow16;
                uint32_t aoff = (uint32_t)arow * 128 + ((kb + lcol) ^ ((uint32_t)(arow & 7) * 16));
                ldsm4(ah[mi], aB + aoff);
            }
            #pragma unroll
            for (int nj = 0; nj < 4; nj++) {
                int brow = wn * 64 + nj * 16 + lrow16;
                uint32_t boff = (uint32_t)brow * 128 + ((kb + lcol) ^ ((uint32_t)(brow & 7) * 16));
                ldsm4(bf[nj], bB + boff);
            }
            #pragma unroll
            for (int nj = 0; nj < 4; nj++)
                #pragma unroll
                for (int mi = 0; mi < 4; mi++) {
                    mma16816(acc[mi][nj * 2 + 0], ah[mi], bf[nj][0], bf[nj][2]);
                    mma16816(acc[mi][nj * 2 + 1], ah[mi], bf[nj][1], bf[nj][3]);
                }
        }
    };

    // ---- prologue: B chunk0 cp.async, pre1 staging, A chunk0 ----
    cpy_B(0, 0);
    {
        float* pre1s = (float*)(smem + SMEM_PRE1);      // pitch 260
        #pragma unroll
        for (int i = 0; i < 16; i++) {
            int idx4 = tid + i * 128;                   // 0..2047 float4 units
            int bb = idx4 >> 6, cc4 = (idx4 & 63) * 4;
            *(float4*)(pre1s + bb * 260 + cc4) = *(const float4*)(g_pre1 + bb * 256 + cc4);
        }
    }
    ldgsts_A_batch(0, 0, 0);
    ldgsts_A_batch(0, 0, 1);
    CP_WAIT0();
    __syncthreads();

    // ---- pipelined mainloop over 4 chunks ----
    #pragma unroll
    for (int c = 0; c < 4; c++) {
        const int buf = c & 1;
        if (c < 3) cpy_B(buf ^ 1, c + 1);      // cp.async: overlaps MMA, 0 regs
        mma_chunk(buf);
        if (c < 3) {
            ldgsts_A_batch(buf ^ 1, c + 1, 0); // short-lived staging regs
            ldgsts_A_batch(buf ^ 1, c + 1, 1);
            CP_WAIT0();
        }
        __syncthreads();
    }

    // ---- epilogue: +pre1 (float2 smem), relu, dot v (ldg float2), reduce ----
    float* pre1s = (float*)(smem + SMEM_PRE1);
    float* ps    = (float*)smem;                        // [64][4] aliases dead As
    #pragma unroll
    for (int mi = 0; mi < 4; mi++) {
        #pragma unroll
        for (int p = 0; p < 2; p++) {
            int row = mi * 16 + (L >> 2) + p * 8;       // 0..63
            int bb  = row & 31;
            const float* pr = pre1s + bb * 260;
            float s = 0.f;
            #pragma unroll
            for (int nj = 0; nj < 8; nj++) {
                int n0 = wn * 64 + nj * 8 + (L & 3) * 2;
                float2 pf = *(const float2*)(pr + n0);
                float2 vv = __ldg((const float2*)(v + n0));
                float e0 = acc[mi][nj][p * 2 + 0] + pf.x;
                float e1 = acc[mi][nj][p * 2 + 1] + pf.y;
                s += fmaxf(e0, 0.f) * vv.x + fmaxf(e1, 0.f) * vv.y;
            }
            s += __shfl_xor_sync(0xffffffffu, s, 1);
            s += __shfl_xor_sync(0xffffffffu, s, 2);
            if ((L & 3) == 0) ps[row * 4 + wn] = s;
        }
    }
    __syncthreads();
    if (tid < 64) {
        float tot = ps[tid * 4] + ps[tid * 4 + 1] + ps[tid * 4 + 2] + ps[tid * 4 + 3];
        g_scores[(size_t)(tid & 31) * TT + blockIdx.x * 2 + (tid >> 5)] = tot;
    }
}

// ---------------------------------------------------------------------------
// Kernel 3: softmax over T per batch row (float4 vectorized).
// ---------------------------------------------------------------------------
__global__ void softmax_kernel(float* __restrict__ out) {
    int b = blockIdx.x, tid = threadIdx.x;
    __shared__ float red[32];
    __shared__ float bc;
    const float4* sc4 = (const float4*)(g_scores + (size_t)b * TT);

    float4 x = sc4[tid];
    float m = fmaxf(fmaxf(x.x, x.y), fmaxf(x.z, x.w));
    #pragma unroll
    for (int o = 16; o; o >>= 1) m = fmaxf(m, __shfl_xor_sync(0xffffffffu, m, o));
    if ((tid & 31) == 0) red[tid >> 5] = m;
    __syncthreads();
    if (tid < 32) {
        float t = red[tid];
        #pragma unroll
        for (int o = 16; o; o >>= 1) t = fmaxf(t, __shfl_xor_sync(0xffffffffu, t, o));
        if (tid == 0) bc = t;
    }
    __syncthreads();
    m = bc;
    float e0 = expf(x.x - m), e1 = expf(x.y - m), e2 = expf(x.z - m), e3 = expf(x.w - m);
    float ssum = (e0 + e1) + (e2 + e3);
    #pragma unroll
    for (int o = 16; o; o >>= 1) ssum += __shfl_xor_sync(0xffffffffu, ssum, o);
    if ((tid & 31) == 0) red[tid >> 5] = ssum;
    __syncthreads();
    if (tid < 32) {
        float t = red[tid];
        #pragma unroll
        for (int o = 16; o; o >>= 1) t += __shfl_xor_sync(0xffffffffu, t, o);
        if (tid == 0) bc = 1.f / t;
    }
    __syncthreads();
    float inv = bc;
    float4* ob4 = (float4*)(out + (size_t)b * TT);
    ob4[tid] = make_float4(e0 * inv, e1 * inv, e2 * inv, e3 * inv);
}

// ---------------------------------------------------------------------------
extern "C" void kernel_launch(void* const* d_in, const int* in_sizes, int n_in,
                              void* d_out, int out_size) {
    const float* hidden = (const float*)d_in[0];   // [B, H]
    const float* enc    = (const float*)d_in[1];   // [T, B, H]
    const float* attn_w = (const float*)d_in[2];   // [H, 2H]
    const float* attn_b = (const float*)d_in[3];   // [H]
    const float* v      = (const float*)d_in[4];   // [H]
    float* out = (float*)d_out;                    // [B, 1, T]

    cudaFuncSetAttribute(energy_kernel,
                         cudaFuncAttributeMaxDynamicSharedMemorySize, SMEM_DYN);

    init_kernel<<<1280, 256>>>(hidden, attn_w, attn_b);
    energy_kernel<<<TB / 64, 128, SMEM_DYN>>>(enc, v);
    softmax_kernel<<<BATCH, 1024>>>(out);
}

// round 14
// speedup vs baseline: 1.5793x; 1.1073x over previous
#include <cuda_runtime.h>
#include <cuda_fp16.h>
#include <cstdint>

// Problem constants
#define BATCH 32
#define TT    4096
#define HH    256
#define TB    (TT * BATCH)     // 131072 rows of enc

// -------------------- scratch (static device arrays) -----------------------
__device__ float g_pre1[BATCH * HH];            // W1*hidden + bias
__device__ float g_scores[BATCH * TT];          // transposed scores [b][t]
// Pre-swizzled B tiles (fp16): [chunk 0..3][256 n][64 k]
__device__ unsigned char g_bpk[4 * 32768];      // 128KB

// -------------------- helpers ----------------------------------------------
__device__ __forceinline__ uint32_t smem_u32(const void* p) {
    uint32_t a;
    asm("{ .reg .u64 t; cvta.to.shared.u64 t, %1; cvt.u32.u64 %0, t; }" : "=r"(a) : "l"(p));
    return a;
}
__device__ __forceinline__ void cp16(void* smem_dst, const void* gsrc) {
    unsigned s = (unsigned)__cvta_generic_to_shared(smem_dst);
    asm volatile("cp.async.cg.shared.global [%0], [%1], 16;\n" :: "r"(s), "l"(gsrc));
}
#define CP_COMMIT() asm volatile("cp.async.commit_group;\n" ::: "memory")
#define CP_WAIT0()  asm volatile("cp.async.wait_group 0;\n" ::: "memory")

__device__ __forceinline__ uint32_t pack_f16x2(float x, float y) {
    uint32_t r;
    asm("cvt.rn.f16x2.f32 %0, %1, %2;" : "=r"(r) : "f"(y), "f"(x));
    return r;
}
__device__ __forceinline__ void ldsm4(uint32_t* r, uint32_t addr) {
    asm volatile("ldmatrix.sync.aligned.m8n8.x4.shared.b16 {%0,%1,%2,%3}, [%4];"
                 : "=r"(r[0]), "=r"(r[1]), "=r"(r[2]), "=r"(r[3]) : "r"(addr));
}
__device__ __forceinline__ void mma16816(float* c, const uint32_t* a, uint32_t b0, uint32_t b1) {
    asm volatile("mma.sync.aligned.m16n8k16.row.col.f32.f16.f16.f32 "
                 "{%0,%1,%2,%3}, {%4,%5,%6,%7}, {%8,%9}, {%0,%1,%2,%3};"
                 : "+f"(c[0]), "+f"(c[1]), "+f"(c[2]), "+f"(c[3])
                 : "r"(a[0]), "r"(a[1]), "r"(a[2]), "r"(a[3]), "r"(b0), "r"(b1));
}

// ---------------------------------------------------------------------------
// Kernel 1 (fused init, PROVEN 1280x256 layout):
//   blocks [0,1024) pre1 (warp per output), [1024,1280) bpack.
// ---------------------------------------------------------------------------
__global__ void init_kernel(const float* __restrict__ hidden,
                            const float* __restrict__ attn_w,
                            const float* __restrict__ attn_b) {
    if (blockIdx.x < 1024) {
        int gw   = (blockIdx.x * 256 + threadIdx.x) >> 5;   // 0..8191
        int lane = threadIdx.x & 31;
        int b = gw >> 8, h = gw & 255;
        const float4* hp = (const float4*)(hidden + (size_t)b * HH);
        const float4* wp = (const float4*)(attn_w + (size_t)h * (2 * HH));
        float4 x0 = hp[lane],      w0 = wp[lane];
        float4 x1 = hp[lane + 32], w1 = wp[lane + 32];
        float s = x0.x*w0.x + x0.y*w0.y + x0.z*w0.z + x0.w*w0.w
                + x1.x*w1.x + x1.y*w1.y + x1.z*w1.z + x1.w*w1.w;
        #pragma unroll
        for (int o = 16; o; o >>= 1) s += __shfl_xor_sync(0xffffffffu, s, o);
        if (lane == 0) g_pre1[gw] = s + attn_b[h];
    } else {
        int idx = (blockIdx.x - 1024) * 256 + threadIdx.x;  // 0..65535
        int c = idx >> 14;
        int r = idx & 16383;
        int n = r >> 6;
        int k = r & 63;
        float val = attn_w[(size_t)n * 512 + 256 + c * 64 + k];
        __half hv = __float2half_rn(val);
        uint32_t o  = (uint32_t)(k * 2) ^ ((uint32_t)(n & 7) * 16);
        uint32_t so = (uint32_t)n * 128 + o;
        *(uint16_t*)(g_bpk + c * 32768 + so) = __half_as_ushort(hv);
    }
}

// ---------------------------------------------------------------------------
// Kernel 2: single-term fp16 HMMA GEMM + fused epilogue.
// CTA: 64 rows x 256 cols, 128 thr (4 warps, wn = wid), warp tile 64x64.
// ALL staging via cp.async (zero register pressure, overlaps MMA):
//   B fp16 pre-swizzled tiles; A fp32 into A32 scratch, converted to fp16
//   A16 tiles by a short smem->smem pass after each MMA block.
// Occupancy 2 (8 warps/SM): 112KB smem/CTA.
// SMEM: A16 [2 buf][64][64] fp16 = 16KB @ 0       (epilogue ps aliases @0)
//       B   [2 buf][256][64] fp16 = 64KB @ 16384
//       A32 [2 buf][64][64] fp32  = 32KB @ 81920
// pre1/v read via __ldg in the epilogue (L1-hot, 32KB).
// ---------------------------------------------------------------------------
#define SMEM_A32 81920
#define SMEM_DYN 114688     // x2 CTAs = 229376 <= 233472 (228KB)

__global__ __launch_bounds__(128, 2)
void energy_kernel(const float* __restrict__ enc, const float* __restrict__ v) {
    extern __shared__ __align__(1024) unsigned char smem[];
    const uint32_t sb = smem_u32(smem);
    const int tid = threadIdx.x, wn = tid >> 5, L = tid & 31;
    const int r0 = blockIdx.x * 64;

    float acc[4][8][4];
    #pragma unroll
    for (int i = 0; i < 4; i++)
        #pragma unroll
        for (int j = 0; j < 8; j++)
            #pragma unroll
            for (int q = 0; q < 4; q++) acc[i][j][q] = 0.f;

    // ---- async stage loaders (no registers held) ----
    auto cpy_B = [&](int buf, int c) {
        #pragma unroll
        for (int st = 0; st < 16; st++) {
            int off = (tid + st * 128) * 16;
            cp16(smem + 16384 + buf * 32768 + off, g_bpk + c * 32768 + off);
        }
    };
    auto cpy_A32 = [&](int buf, int c) {
        // 64 rows x 64 floats = 1024 x 16B; 8 per thread
        #pragma unroll
        for (int st = 0; st < 8; st++) {
            int idx = tid + st * 128;              // 0..1023
            int row = idx >> 4, c16 = idx & 15;
            cp16(smem + SMEM_A32 + buf * 16384 + row * 256 + c16 * 16,
                 enc + (size_t)(r0 + row) * HH + c * 64 + c16 * 4);
        }
    };
    // smem fp32 -> fp16 swizzled tile (short LDS->cvt->STS, 29cyc latency)
    auto convert_A = [&](int buf) {
        const float* a32 = (const float*)(smem + SMEM_A32 + buf * 16384);
        #pragma unroll
        for (int i = 0; i < 4; i++) {
            int u = tid + i * 128;                 // 0..511 (8-float units)
            int row = u >> 3, c8 = u & 7;
            const float4* p = (const float4*)(a32 + row * 64 + c8 * 8);
            float4 a0 = p[0], a1 = p[1];
            uint4 hv = make_uint4(pack_f16x2(a0.x, a0.y), pack_f16x2(a0.z, a0.w),
                                  pack_f16x2(a1.x, a1.y), pack_f16x2(a1.z, a1.w));
            uint32_t off = (uint32_t)row * 128 + (((uint32_t)c8 * 16) ^ ((uint32_t)(row & 7) * 16));
            *(uint4*)(smem + buf * 8192 + off) = hv;
        }
    };

    const int lrow16 = L & 15;
    const uint32_t lcol = (uint32_t)(L >> 4) * 16;

    auto mma_chunk = [&](int buf) {
        const uint32_t aB = sb + (uint32_t)buf * 8192;
        const uint32_t bB = sb + 16384u + (uint32_t)buf * 32768;
        #pragma unroll
        for (int ks = 0; ks < 4; ks++) {
            const uint32_t kb = (uint32_t)ks * 32;
            uint32_t ah[4][4], bf[4][4];
            #pragma unroll
            for (int mi = 0; mi < 4; mi++) {
                int arow = mi * 16 + lrow16;
                uint32_t aoff = (uint32_t)arow * 128 + ((kb + lcol) ^ ((uint32_t)(arow & 7) * 16));
                ldsm4(ah[mi], aB + aoff);
            }
            #pragma unroll
            for (int nj = 0; nj < 4; nj++) {
                int brow = wn * 64 + nj * 16 + lrow16;
                uint32_t boff = (uint32_t)brow * 128 + ((kb + lcol) ^ ((uint32_t)(brow & 7) * 16));
                ldsm4(bf[nj], bB + boff);
            }
            #pragma unroll
            for (int nj = 0; nj < 4; nj++)
                #pragma unroll
                for (int mi = 0; mi < 4; mi++) {
                    mma16816(acc[mi][nj * 2 + 0], ah[mi], bf[nj][0], bf[nj][2]);
                    mma16816(acc[mi][nj * 2 + 1], ah[mi], bf[nj][1], bf[nj][3]);
                }
        }
    };

    // ---- prologue: chunk 0 stages ----
    cpy_B(0, 0);
    cpy_A32(0, 0);
    CP_COMMIT();
    CP_WAIT0();
    __syncthreads();            // A32 visible to all before convert
    convert_A(0);
    __syncthreads();

    // ---- pipelined mainloop over 4 chunks ----
    #pragma unroll
    for (int c = 0; c < 4; c++) {
        const int buf = c & 1;
        if (c < 3) {
            cpy_B(buf ^ 1, c + 1);      // async, overlaps MMA
            cpy_A32(buf ^ 1, c + 1);    // async, overlaps MMA
            CP_COMMIT();
        }
        mma_chunk(buf);
        if (c < 3) {
            CP_WAIT0();                 // stages arrived during MMA
            __syncthreads();            // all warps past ldsm of buf; A32 visible
            convert_A(buf ^ 1);         // short smem->smem pass
        }
        __syncthreads();
    }

    // ---- epilogue: +pre1 (__ldg, L1-hot), relu, dot v, reduce, store ----
    float* ps = (float*)smem;                        // [64][4] aliases dead A16
    #pragma unroll
    for (int mi = 0; mi < 4; mi++) {
        #pragma unroll
        for (int p = 0; p < 2; p++) {
            int row = mi * 16 + (L >> 2) + p * 8;    // 0..63
            int bb  = row & 31;
            const float* pr = g_pre1 + bb * 256;
            float s = 0.f;
            #pragma unroll
            for (int nj = 0; nj < 8; nj++) {
                int n0 = wn * 64 + nj * 8 + (L & 3) * 2;
                float2 pf = __ldg((const float2*)(pr + n0));
                float2 vv = __ldg((const float2*)(v + n0));
                float e0 = acc[mi][nj][p * 2 + 0] + pf.x;
                float e1 = acc[mi][nj][p * 2 + 1] + pf.y;
                s += fmaxf(e0, 0.f) * vv.x + fmaxf(e1, 0.f) * vv.y;
            }
            s += __shfl_xor_sync(0xffffffffu, s, 1);
            s += __shfl_xor_sync(0xffffffffu, s, 2);
            if ((L & 3) == 0) ps[row * 4 + wn] = s;
        }
    }
    __syncthreads();
    if (tid < 64) {
        float tot = ps[tid * 4] + ps[tid * 4 + 1] + ps[tid * 4 + 2] + ps[tid * 4 + 3];
        g_scores[(size_t)(tid & 31) * TT + blockIdx.x * 2 + (tid >> 5)] = tot;
    }
}

// ---------------------------------------------------------------------------
// Kernel 3: softmax over T per batch row (float4 vectorized).
// ---------------------------------------------------------------------------
__global__ void softmax_kernel(float* __restrict__ out) {
    int b = blockIdx.x, tid = threadIdx.x;
    __shared__ float red[32];
    __shared__ float bc;
    const float4* sc4 = (const float4*)(g_scores + (size_t)b * TT);

    float4 x = sc4[tid];
    float m = fmaxf(fmaxf(x.x, x.y), fmaxf(x.z, x.w));
    #pragma unroll
    for (int o = 16; o; o >>= 1) m = fmaxf(m, __shfl_xor_sync(0xffffffffu, m, o));
    if ((tid & 31) == 0) red[tid >> 5] = m;
    __syncthreads();
    if (tid < 32) {
        float t = red[tid];
        #pragma unroll
        for (int o = 16; o; o >>= 1) t = fmaxf(t, __shfl_xor_sync(0xffffffffu, t, o));
        if (tid == 0) bc = t;
    }
    __syncthreads();
    m = bc;
    float e0 = expf(x.x - m), e1 = expf(x.y - m), e2 = expf(x.z - m), e3 = expf(x.w - m);
    float ssum = (e0 + e1) + (e2 + e3);
    #pragma unroll
    for (int o = 16; o; o >>= 1) ssum += __shfl_xor_sync(0xffffffffu, ssum, o);
    if ((tid & 31) == 0) red[tid >> 5] = ssum;
    __syncthreads();
    if (tid < 32) {
        float t = red[tid];
        #pragma unroll
        for (int o = 16; o; o >>= 1) t += __shfl_xor_sync(0xffffffffu, t, o);
        if (tid == 0) bc = 1.f / t;
    }
    __syncthreads();
    float inv = bc;
    float4* ob4 = (float4*)(out + (size_t)b * TT);
    ob4[tid] = make_float4(e0 * inv, e1 * inv, e2 * inv, e3 * inv);
}

// ---------------------------------------------------------------------------
extern "C" void kernel_launch(void* const* d_in, const int* in_sizes, int n_in,
                              void* d_out, int out_size) {
    const float* hidden = (const float*)d_in[0];   // [B, H]
    const float* enc    = (const float*)d_in[1];   // [T, B, H]
    const float* attn_w = (const float*)d_in[2];   // [H, 2H]
    const float* attn_b = (const float*)d_in[3];   // [H]
    const float* v      = (const float*)d_in[4];   // [H]
    float* out = (float*)d_out;                    // [B, 1, T]

    cudaFuncSetAttribute(energy_kernel,
                         cudaFuncAttributeMaxDynamicSharedMemorySize, SMEM_DYN);

    init_kernel<<<1280, 256>>>(hidden, attn_w, attn_b);
    energy_kernel<<<TB / 64, 128, SMEM_DYN>>>(enc, v);
    softmax_kernel<<<BATCH, 1024>>>(out);
}